// round 5
// baseline (speedup 1.0000x reference)
#include <cuda_runtime.h>
#include <math.h>

#define RES_UP 0.05f
#define RES_DN 0.02f
#define REQ_UP 0.02f
#define REQ_DN 0.02f

#define MAXG 64

typedef unsigned long long u64;

// per-LP objective partials (B*T <= 8192)
__device__ float g_partial[8192];

// ---------- packed f32x2 helpers (sm_100+), u64-primary ----------
__device__ __forceinline__ u64 pk(float lo, float hi) {
    u64 r; asm("mov.b64 %0, {%1,%2};" : "=l"(r) : "f"(lo), "f"(hi)); return r;
}
__device__ __forceinline__ void upk(u64 p, float& lo, float& hi) {
    asm("mov.b64 {%0,%1}, %2;" : "=f"(lo), "=f"(hi) : "l"(p));
}
__device__ __forceinline__ u64 f2add(u64 a, u64 b) {
    u64 r; asm("add.rn.f32x2 %0, %1, %2;" : "=l"(r) : "l"(a), "l"(b)); return r;
}
__device__ __forceinline__ u64 f2fma(u64 a, u64 b, u64 c) {
    u64 r; asm("fma.rn.f32x2 %0, %1, %2, %3;" : "=l"(r) : "l"(a), "l"(b), "l"(c)); return r;
}
__device__ __forceinline__ u64 f2sub(u64 a, u64 b) {
    const u64 N1 = 0xBF800000BF800000ULL;  // (-1.0f, -1.0f)
    return f2fma(b, N1, a);                // a - b (exact)
}
__device__ __forceinline__ u64 f2relu(u64 a) {
    float lo, hi; upk(a, lo, hi);
    return pk(fmaxf(lo, 0.f), fmaxf(hi, 0.f));
}

// One 16-lane group per LP; 2 LPs per warp; 4 gen slots/lane = 2 packed pairs.
// Pair p holds gens (32p + gl) [lo] and (32p + 16 + gl) [hi]. Dead gens (g>=G)
// use poisoned constants (b=1e30, pmax=pmin=0) which pin their state at 0.
__global__ __launch_bounds__(32) void pdhg_kernel(
    const float* __restrict__ forecast, const float* __restrict__ pminv,
    const float* __restrict__ pmaxv, const float* __restrict__ bv,
    const float* __restrict__ cv, const int* __restrict__ nitp,
    float* __restrict__ out, int G, int B, int T, float tau)
{
    const int lane = threadIdx.x;
    const int grp  = lane >> 4;
    const int gl   = lane & 15;
    const int NP   = B * T;
    const int lp   = blockIdx.x * 2 + grp;
    const bool live = lp < NP;
    const int lpc  = live ? lp : NP - 1;
    const float D  = forecast[lpc];
    const int nit  = *nitp;
    const float sig = tau;

    u64 tb[2], tcu[2], tcd[2], spx[2], spn[2];
#pragma unroll
    for (int p = 0; p < 2; ++p) {
        int glo = 32 * p + gl, ghi = glo + 16;
        float blo  = (glo < G) ? bv[glo]    : 1e30f;
        float bhi  = (ghi < G) ? bv[ghi]    : 1e30f;
        float pxlo = (glo < G) ? pmaxv[glo] : 0.f;
        float pxhi = (ghi < G) ? pmaxv[ghi] : 0.f;
        float pnlo = (glo < G) ? pminv[glo] : 0.f;
        float pnhi = (ghi < G) ? pminv[ghi] : 0.f;
        tb[p]  = pk(tau * blo,          tau * bhi);
        tcu[p] = pk(tau * RES_UP * blo, tau * RES_UP * bhi);
        tcd[p] = pk(tau * RES_DN * blo, tau * RES_DN * bhi);
        spx[p] = pk(sig * pxlo,         sig * pxhi);
        spn[p] = pk(sig * pnlo,         sig * pnhi);
    }
    const u64 NTAU = pk(-tau, -tau);
    const u64 SIGp = pk(sig, sig);
    const u64 NSIG = pk(-sig, -sig);
    const float ruD = REQ_UP * D, rdD = REQ_DN * D;

    // packed state
    u64 P[2]  = {0, 0}, Ru[2] = {0, 0}, Rd[2] = {0, 0};
    u64 av[2] = {0, 0}, dv[2] = {0, 0}, uv[2] = {0, 0}, lv[2] = {0, 0};
    float y0 = 0.f, yu = 0.f, yd = 0.f;

    for (int it = 0; it < nit; ++it) {
        u64 ty0p = pk(tau * y0, tau * y0);
        u64 tyup = pk(tau * yu, tau * yu);
        u64 tydp = pk(tau * yd, tau * yd);
        u64 Pb[2], Rub[2], Rdb[2];
#pragma unroll
        for (int p = 0; p < 2; ++p) {
            // x_new = relu(x - tau*(c_obj + K^T y))
            u64 t1 = f2sub(av[p], dv[p]);
            u64 t2 = f2sub(uv[p], lv[p]);
            u64 t3 = f2add(t1, t2);
            u64 e  = f2sub(P[p], tb[p]);
            e = f2sub(e, ty0p);
            e = f2fma(NTAU, t3, e);
            u64 Pn = f2relu(e);

            e = f2sub(Ru[p], tcu[p]);
            e = f2fma(NTAU, av[p], e);
            e = f2add(e, tyup);
            u64 Run = f2relu(e);

            e = f2sub(Rd[p], tcd[p]);
            e = f2fma(NTAU, dv[p], e);
            e = f2add(e, tydp);
            u64 Rdn = f2relu(e);

            // x_bar = 2*x_new - x_old
            Pb[p]  = f2sub(f2add(Pn, Pn),   P[p]);
            Rub[p] = f2sub(f2add(Run, Run), Ru[p]);
            Rdb[p] = f2sub(f2add(Rdn, Rdn), Rd[p]);
            P[p] = Pn; Ru[p] = Run; Rd[p] = Rdn;
        }

        // lane-local partial sums
        float sP, sRu, sRd;
        { u64 s = f2add(Pb[0],  Pb[1]);  float x, y; upk(s, x, y); sP  = x + y; }
        { u64 s = f2add(Rub[0], Rub[1]); float x, y; upk(s, x, y); sRu = x + y; }
        { u64 s = f2add(Rdb[0], Rdb[1]); float x, y; upk(s, x, y); sRd = x + y; }

        // 4-stage butterfly over the 16-lane group; dual updates (independent
        // of the sums) are woven between the stages to fill SHFL latency.
        sP  += __shfl_xor_sync(0xffffffffu, sP,  8);
        sRu += __shfl_xor_sync(0xffffffffu, sRu, 8);
        sRd += __shfl_xor_sync(0xffffffffu, sRd, 8);
        {   // pair 0: a, d
            u64 t = f2add(Pb[0], Rub[0]);
            av[0] = f2relu(f2fma(SIGp, t, f2sub(av[0], spx[0])));
            t = f2sub(Rdb[0], Pb[0]);
            dv[0] = f2relu(f2fma(SIGp, t, f2add(dv[0], spn[0])));
        }
        sP  += __shfl_xor_sync(0xffffffffu, sP,  4);
        sRu += __shfl_xor_sync(0xffffffffu, sRu, 4);
        sRd += __shfl_xor_sync(0xffffffffu, sRd, 4);
        {   // pair 0: u, l
            uv[0] = f2relu(f2fma(SIGp, Pb[0], f2sub(uv[0], spx[0])));
            lv[0] = f2relu(f2fma(NSIG, Pb[0], f2add(lv[0], spn[0])));
        }
        sP  += __shfl_xor_sync(0xffffffffu, sP,  2);
        sRu += __shfl_xor_sync(0xffffffffu, sRu, 2);
        sRd += __shfl_xor_sync(0xffffffffu, sRd, 2);
        {   // pair 1: a, d
            u64 t = f2add(Pb[1], Rub[1]);
            av[1] = f2relu(f2fma(SIGp, t, f2sub(av[1], spx[1])));
            t = f2sub(Rdb[1], Pb[1]);
            dv[1] = f2relu(f2fma(SIGp, t, f2add(dv[1], spn[1])));
        }
        sP  += __shfl_xor_sync(0xffffffffu, sP,  1);
        sRu += __shfl_xor_sync(0xffffffffu, sRu, 1);
        sRd += __shfl_xor_sync(0xffffffffu, sRd, 1);
        {   // pair 1: u, l
            uv[1] = f2relu(f2fma(SIGp, Pb[1], f2sub(uv[1], spx[1])));
            lv[1] = f2relu(f2fma(NSIG, Pb[1], f2add(lv[1], spn[1])));
        }

        // scalar dual rows
        y0 = fmaf(sig, sP - D, y0);
        yu = fmaxf(fmaf(sig, ruD - sRu, yu), 0.f);
        yd = fmaxf(fmaf(sig, rdD - sRd, yd), 0.f);
    }

    // outputs: P_DA | R_up | R_dn | obj | Cost_DA, all (B, G, T)
    size_t BGT = (size_t)B * G * T;
    float* Pout = out;
    float* Ruo  = out + BGT;
    float* Rdo  = out + 2 * BGT;
    float* Co   = out + 3 * BGT + B;
    const int bb = lpc / T, t = lpc - bb * T;

    float part = 0.f;
    if (live) {
#pragma unroll
        for (int p = 0; p < 2; ++p) {
            float Plo, Phi, Rulo, Ruhi, Rdlo, Rdhi;
            upk(P[p], Plo, Phi);
            upk(Ru[p], Rulo, Ruhi);
            upk(Rd[p], Rdlo, Rdhi);
            int glo = 32 * p + gl, ghi = glo + 16;
            if (glo < G) {
                size_t i = ((size_t)bb * G + glo) * T + t;
                float bg = bv[glo];
                float co = fmaf(bg, Plo, cv[glo]);
                Pout[i] = Plo; Ruo[i] = Rulo; Rdo[i] = Rdlo; Co[i] = co;
                part += co + RES_UP * bg * Rulo + RES_DN * bg * Rdlo;
            }
            if (ghi < G) {
                size_t i = ((size_t)bb * G + ghi) * T + t;
                float bg = bv[ghi];
                float co = fmaf(bg, Phi, cv[ghi]);
                Pout[i] = Phi; Ruo[i] = Ruhi; Rdo[i] = Rdhi; Co[i] = co;
                part += co + RES_UP * bg * Ruhi + RES_DN * bg * Rdhi;
            }
        }
    }
#pragma unroll
    for (int k = 8; k > 0; k >>= 1)
        part += __shfl_xor_sync(0xffffffffu, part, k);
    if (live && gl == 0) g_partial[lp] = part;
}

// Sum T per-LP partials -> obj[b]. One warp per batch element.
__global__ __launch_bounds__(32) void obj_kernel(
    float* __restrict__ out, int G, int B, int T)
{
    int bb = blockIdx.x;
    int lane = threadIdx.x;
    size_t BGT = (size_t)B * G * T;
    float v = (lane < T) ? g_partial[bb * T + lane] : 0.f;
#pragma unroll
    for (int k = 16; k > 0; k >>= 1)
        v += __shfl_xor_sync(0xffffffffu, v, k);
    if (lane == 0) out[3 * BGT + bb] = v;
}

// ---------------- host: structured spectral norm of K (power iteration) -----
static void K_matvec(const double* v, double* w, int G) {
    int n1 = G, n2 = 2 * G;
    double s0 = 0, s1 = 0, s2 = 0;
    for (int g = 0; g < G; ++g) { s0 += v[g]; s1 += v[n1 + g]; s2 += v[n2 + g]; }
    w[0] = s0;
    for (int g = 0; g < G; ++g) {
        w[1 + g]          =  v[g] + v[n1 + g];
        w[1 + G + g]      = -v[g] + v[n2 + g];
        w[1 + 2 * G + g]  =  v[g];
        w[1 + 3 * G + g]  = -v[g];
    }
    w[1 + 4 * G]     = -s1;
    w[1 + 4 * G + 1] = -s2;
}

static void KT_matvec(const double* w, double* z, int G) {
    double yu = w[1 + 4 * G], yd = w[1 + 4 * G + 1];
    for (int g = 0; g < G; ++g) {
        z[g]           = w[0] + w[1 + g] - w[1 + G + g] + w[1 + 2 * G + g] - w[1 + 3 * G + g];
        z[G + g]       = w[1 + g] - yu;
        z[2 * G + g]   = w[1 + G + g] - yd;
    }
}

static double spectral_norm_K(int G) {
    static double v[3 * MAXG], w[4 * MAXG + 3], z[3 * MAXG];
    int n = 3 * G;
    for (int i = 0; i < n; ++i) v[i] = 1.0 + 0.001 * (double)(i % 7);
    double lam = 1.0;
    for (int it = 0; it < 4000; ++it) {
        K_matvec(v, w, G);
        KT_matvec(w, z, G);
        double nrm = 0.0;
        for (int i = 0; i < n; ++i) nrm += z[i] * z[i];
        nrm = sqrt(nrm);
        lam = nrm;
        double inv = 1.0 / nrm;
        for (int i = 0; i < n; ++i) v[i] = z[i] * inv;
    }
    return sqrt(lam);  // sigma_max(K)
}

extern "C" void kernel_launch(void* const* d_in, const int* in_sizes, int n_in,
                              void* d_out, int out_size) {
    const float* forecast = (const float*)d_in[0];
    const float* pminv    = (const float*)d_in[1];
    const float* pmaxv    = (const float*)d_in[2];
    const float* bv       = (const float*)d_in[3];
    const float* cv       = (const float*)d_in[4];
    const int*   nitp     = (const int*)d_in[5];

    int G  = in_sizes[1];
    int BT = in_sizes[0];
    // out_size = 4*B*G*T + B  with  B*T = BT  ->  B = out_size - 4*G*BT
    int B = out_size - 4 * G * BT;
    if (B <= 0) B = 1;
    int T = BT / B;

    double L = spectral_norm_K(G);
    float tau = (float)(0.9 / L);

    float* out = (float*)d_out;
    int blocks = (BT + 1) / 2;  // 2 LPs per 32-thread block (one warp)
    pdhg_kernel<<<blocks, 32>>>(
        forecast, pminv, pmaxv, bv, cv, nitp, out, G, B, T, tau);
    obj_kernel<<<B, 32>>>(out, G, B, T);
}

// round 6
// speedup vs baseline: 1.1786x; 1.1786x over previous
#include <cuda_runtime.h>
#include <math.h>

#define RES_UP 0.05f
#define RES_DN 0.02f
#define REQ_UP 0.02f
#define REQ_DN 0.02f

#define MAXG 64

// ---------- packed f32x2 helpers: floats in/out, pack inside asm ----------
// r = a*b + c   (elementwise on the pair)
__device__ __forceinline__ void F2FMA(float& r0, float& r1,
    float a0, float a1, float b0, float b1, float c0, float c1) {
    asm("{\n\t.reg .b64 ra, rb, rc;\n\t"
        "mov.b64 ra, {%2,%3};\n\tmov.b64 rb, {%4,%5};\n\tmov.b64 rc, {%6,%7};\n\t"
        "fma.rn.f32x2 rc, ra, rb, rc;\n\tmov.b64 {%0,%1}, rc;\n\t}"
        : "=f"(r0), "=f"(r1)
        : "f"(a0), "f"(a1), "f"(b0), "f"(b1), "f"(c0), "f"(c1));
}
// r = a + b
__device__ __forceinline__ void F2ADD(float& r0, float& r1,
    float a0, float a1, float b0, float b1) {
    asm("{\n\t.reg .b64 ra, rb;\n\t"
        "mov.b64 ra, {%2,%3};\n\tmov.b64 rb, {%4,%5};\n\t"
        "add.rn.f32x2 ra, ra, rb;\n\tmov.b64 {%0,%1}, ra;\n\t}"
        : "=f"(r0), "=f"(r1)
        : "f"(a0), "f"(a1), "f"(b0), "f"(b1));
}
// r = a - b  (exact: fma(b,-1,a))
#define F2SUB(r0, r1, a0, a1, b0, b1) F2FMA(r0, r1, b0, b1, -1.f, -1.f, a0, a1)

// Fused: one block per batch element b. ceil(T/2) warps; each 16-lane group
// owns one LP (timestep). 4 gen slots/lane (g = 16*s + gl). Dead gens (g>=G)
// use poisoned constants (b=1e30, pmax=pmin=0) which pin their state at 0.
// Objective is reduced block-wide in the epilogue via smem.
__global__ __launch_bounds__(512) void pdhg_fused_kernel(
    const float* __restrict__ forecast, const float* __restrict__ pminv,
    const float* __restrict__ pmaxv, const float* __restrict__ bv,
    const float* __restrict__ cv, const int* __restrict__ nitp,
    float* __restrict__ out, int G, int B, int T, float tau)
{
    __shared__ float sobj[64];
    const int bb   = blockIdx.x;
    const int w    = threadIdx.x >> 5;
    const int grp  = (threadIdx.x >> 4) & 1;
    const int gl   = threadIdx.x & 15;
    const int t    = 2 * w + grp;
    const bool live = t < T;
    const int tc   = live ? t : T - 1;
    const float D  = forecast[bb * T + tc];
    const int nit  = *nitp;
    const float sig = tau;
    const float ntau = -tau, nsig = -sig;
    const float ruD = REQ_UP * D, rdD = REQ_DN * D;

    float tb[4], tcu[4], tcd[4], spx[4], spn[4];
#pragma unroll
    for (int s = 0; s < 4; ++s) {
        int g = 16 * s + gl;
        float bg = (g < G) ? bv[g]    : 1e30f;
        float px = (g < G) ? pmaxv[g] : 0.f;
        float pn = (g < G) ? pminv[g] : 0.f;
        tb[s]  = tau * bg;
        tcu[s] = tau * RES_UP * bg;
        tcd[s] = tau * RES_DN * bg;
        spx[s] = sig * px;
        spn[s] = sig * pn;
    }

    // state
    float P[4]  = {0,0,0,0}, Ru[4] = {0,0,0,0}, Rd[4] = {0,0,0,0};
    float av[4] = {0,0,0,0}, dv[4] = {0,0,0,0}, uv[4] = {0,0,0,0}, lv[4] = {0,0,0,0};
    float y0 = 0.f, yu = 0.f, yd = 0.f;

    for (int it = 0; it < nit; ++it) {
        const float nty0 = ntau * y0;
        const float tyu  = tau * yu;
        const float tyd  = tau * yd;

        float Pb[4], Rub[4], Rdb[4];
#pragma unroll
        for (int q = 0; q < 2; ++q) {
            const int i = 2 * q, j = i + 1;
            float t0, t1, s0, s1, e0, e1;
            // t = a - d + u - l
            F2SUB(t0, t1, av[i], av[j], dv[i], dv[j]);
            F2SUB(s0, s1, uv[i], uv[j], lv[i], lv[j]);
            F2ADD(t0, t1, t0, t1, s0, s1);
            // P_new = relu(P - tau*b - tau*y0 - tau*t)
            F2SUB(e0, e1, P[i], P[j], tb[i], tb[j]);
            F2ADD(e0, e1, e0, e1, nty0, nty0);
            F2FMA(e0, e1, t0, t1, ntau, ntau, e0, e1);
            float Pn0 = fmaxf(e0, 0.f), Pn1 = fmaxf(e1, 0.f);
            // Ru_new = relu(Ru - tau*cu - tau*a + tau*yu)
            F2SUB(e0, e1, Ru[i], Ru[j], tcu[i], tcu[j]);
            F2ADD(e0, e1, e0, e1, tyu, tyu);
            F2FMA(e0, e1, av[i], av[j], ntau, ntau, e0, e1);
            float Run0 = fmaxf(e0, 0.f), Run1 = fmaxf(e1, 0.f);
            // Rd_new = relu(Rd - tau*cd - tau*d + tau*yd)
            F2SUB(e0, e1, Rd[i], Rd[j], tcd[i], tcd[j]);
            F2ADD(e0, e1, e0, e1, tyd, tyd);
            F2FMA(e0, e1, dv[i], dv[j], ntau, ntau, e0, e1);
            float Rdn0 = fmaxf(e0, 0.f), Rdn1 = fmaxf(e1, 0.f);
            // x_bar = 2*x_new - x_old
            F2ADD(e0, e1, Pn0, Pn1, Pn0, Pn1);
            F2SUB(Pb[i], Pb[j], e0, e1, P[i], P[j]);
            F2ADD(e0, e1, Run0, Run1, Run0, Run1);
            F2SUB(Rub[i], Rub[j], e0, e1, Ru[i], Ru[j]);
            F2ADD(e0, e1, Rdn0, Rdn1, Rdn0, Rdn1);
            F2SUB(Rdb[i], Rdb[j], e0, e1, Rd[i], Rd[j]);
            P[i] = Pn0; P[j] = Pn1; Ru[i] = Run0; Ru[j] = Run1; Rd[i] = Rdn0; Rd[j] = Rdn1;
        }

        // lane-local partial sums
        float sP, sRu, sRd, h0, h1;
        F2ADD(h0, h1, Pb[0], Pb[1], Pb[2], Pb[3]);     sP  = h0 + h1;
        F2ADD(h0, h1, Rub[0], Rub[1], Rub[2], Rub[3]); sRu = h0 + h1;
        F2ADD(h0, h1, Rdb[0], Rdb[1], Rdb[2], Rdb[3]); sRd = h0 + h1;

        // 4-stage butterfly over the 16-lane group; dual updates interleaved.
        sP  += __shfl_xor_sync(0xffffffffu, sP,  8);
        sRu += __shfl_xor_sync(0xffffffffu, sRu, 8);
        sRd += __shfl_xor_sync(0xffffffffu, sRd, 8);
        {   // pair 0: a, d
            float t0, t1, e0, e1;
            F2ADD(t0, t1, Pb[0], Pb[1], Rub[0], Rub[1]);
            F2SUB(e0, e1, av[0], av[1], spx[0], spx[1]);
            F2FMA(e0, e1, t0, t1, sig, sig, e0, e1);
            av[0] = fmaxf(e0, 0.f); av[1] = fmaxf(e1, 0.f);
            F2SUB(t0, t1, Rdb[0], Rdb[1], Pb[0], Pb[1]);
            F2ADD(e0, e1, dv[0], dv[1], spn[0], spn[1]);
            F2FMA(e0, e1, t0, t1, sig, sig, e0, e1);
            dv[0] = fmaxf(e0, 0.f); dv[1] = fmaxf(e1, 0.f);
        }
        sP  += __shfl_xor_sync(0xffffffffu, sP,  4);
        sRu += __shfl_xor_sync(0xffffffffu, sRu, 4);
        sRd += __shfl_xor_sync(0xffffffffu, sRd, 4);
        {   // pair 0: u, l
            float e0, e1;
            F2SUB(e0, e1, uv[0], uv[1], spx[0], spx[1]);
            F2FMA(e0, e1, Pb[0], Pb[1], sig, sig, e0, e1);
            uv[0] = fmaxf(e0, 0.f); uv[1] = fmaxf(e1, 0.f);
            F2ADD(e0, e1, lv[0], lv[1], spn[0], spn[1]);
            F2FMA(e0, e1, Pb[0], Pb[1], nsig, nsig, e0, e1);
            lv[0] = fmaxf(e0, 0.f); lv[1] = fmaxf(e1, 0.f);
        }
        sP  += __shfl_xor_sync(0xffffffffu, sP,  2);
        sRu += __shfl_xor_sync(0xffffffffu, sRu, 2);
        sRd += __shfl_xor_sync(0xffffffffu, sRd, 2);
        {   // pair 1: a, d
            float t0, t1, e0, e1;
            F2ADD(t0, t1, Pb[2], Pb[3], Rub[2], Rub[3]);
            F2SUB(e0, e1, av[2], av[3], spx[2], spx[3]);
            F2FMA(e0, e1, t0, t1, sig, sig, e0, e1);
            av[2] = fmaxf(e0, 0.f); av[3] = fmaxf(e1, 0.f);
            F2SUB(t0, t1, Rdb[2], Rdb[3], Pb[2], Pb[3]);
            F2ADD(e0, e1, dv[2], dv[3], spn[2], spn[3]);
            F2FMA(e0, e1, t0, t1, sig, sig, e0, e1);
            dv[2] = fmaxf(e0, 0.f); dv[3] = fmaxf(e1, 0.f);
        }
        sP  += __shfl_xor_sync(0xffffffffu, sP,  1);
        sRu += __shfl_xor_sync(0xffffffffu, sRu, 1);
        sRd += __shfl_xor_sync(0xffffffffu, sRd, 1);
        {   // pair 1: u, l
            float e0, e1;
            F2SUB(e0, e1, uv[2], uv[3], spx[2], spx[3]);
            F2FMA(e0, e1, Pb[2], Pb[3], sig, sig, e0, e1);
            uv[2] = fmaxf(e0, 0.f); uv[3] = fmaxf(e1, 0.f);
            F2ADD(e0, e1, lv[2], lv[3], spn[2], spn[3]);
            F2FMA(e0, e1, Pb[2], Pb[3], nsig, nsig, e0, e1);
            lv[2] = fmaxf(e0, 0.f); lv[3] = fmaxf(e1, 0.f);
        }

        // scalar rows
        y0 = fmaf(sig, sP - D, y0);
        yu = fmaxf(fmaf(nsig, sRu, fmaf(sig, ruD, yu)), 0.f);
        yd = fmaxf(fmaf(nsig, sRd, fmaf(sig, rdD, yd)), 0.f);
    }

    // outputs: P_DA | R_up | R_dn | obj | Cost_DA, all (B, G, T)
    size_t BGT = (size_t)B * G * T;
    float* Pout = out;
    float* Ruo  = out + BGT;
    float* Rdo  = out + 2 * BGT;
    float* Co   = out + 3 * BGT + B;

    float part = 0.f;
    if (live) {
#pragma unroll
        for (int s = 0; s < 4; ++s) {
            int g = 16 * s + gl;
            if (g < G) {
                size_t i = ((size_t)bb * G + g) * T + t;
                float bg = bv[g];
                float co = fmaf(bg, P[s], cv[g]);
                Pout[i] = P[s]; Ruo[i] = Ru[s]; Rdo[i] = Rd[s]; Co[i] = co;
                part += co + RES_UP * bg * Ru[s] + RES_DN * bg * Rd[s];
            }
        }
    }
#pragma unroll
    for (int k = 8; k > 0; k >>= 1)
        part += __shfl_xor_sync(0xffffffffu, part, k);
    if (live && gl == 0) sobj[t] = part;
    __syncthreads();

    // block reduction of T per-LP partials -> obj[bb] (warp 0 only)
    if (w == 0) {
        int lane = threadIdx.x & 31;
        float v = (lane < T) ? sobj[lane] : 0.f;
        // T may exceed 32? assume T <= 64: fold second half
        if (32 + lane < T) v += sobj[32 + lane];
#pragma unroll
        for (int k = 16; k > 0; k >>= 1)
            v += __shfl_xor_sync(0xffffffffu, v, k);
        if (lane == 0) out[3 * BGT + bb] = v;
    }
}

// ---------------- host: structured spectral norm of K (power iteration) -----
static void K_matvec(const double* v, double* w, int G) {
    int n1 = G, n2 = 2 * G;
    double s0 = 0, s1 = 0, s2 = 0;
    for (int g = 0; g < G; ++g) { s0 += v[g]; s1 += v[n1 + g]; s2 += v[n2 + g]; }
    w[0] = s0;
    for (int g = 0; g < G; ++g) {
        w[1 + g]          =  v[g] + v[n1 + g];
        w[1 + G + g]      = -v[g] + v[n2 + g];
        w[1 + 2 * G + g]  =  v[g];
        w[1 + 3 * G + g]  = -v[g];
    }
    w[1 + 4 * G]     = -s1;
    w[1 + 4 * G + 1] = -s2;
}

static void KT_matvec(const double* w, double* z, int G) {
    double yu = w[1 + 4 * G], yd = w[1 + 4 * G + 1];
    for (int g = 0; g < G; ++g) {
        z[g]           = w[0] + w[1 + g] - w[1 + G + g] + w[1 + 2 * G + g] - w[1 + 3 * G + g];
        z[G + g]       = w[1 + g] - yu;
        z[2 * G + g]   = w[1 + G + g] - yd;
    }
}

static double spectral_norm_K(int G) {
    static double v[3 * MAXG], w[4 * MAXG + 3], z[3 * MAXG];
    int n = 3 * G;
    for (int i = 0; i < n; ++i) v[i] = 1.0 + 0.001 * (double)(i % 7);
    double lam = 1.0;
    for (int it = 0; it < 4000; ++it) {
        K_matvec(v, w, G);
        KT_matvec(w, z, G);
        double nrm = 0.0;
        for (int i = 0; i < n; ++i) nrm += z[i] * z[i];
        nrm = sqrt(nrm);
        lam = nrm;
        double inv = 1.0 / nrm;
        for (int i = 0; i < n; ++i) v[i] = z[i] * inv;
    }
    return sqrt(lam);  // sigma_max(K)
}

extern "C" void kernel_launch(void* const* d_in, const int* in_sizes, int n_in,
                              void* d_out, int out_size) {
    const float* forecast = (const float*)d_in[0];
    const float* pminv    = (const float*)d_in[1];
    const float* pmaxv    = (const float*)d_in[2];
    const float* bv       = (const float*)d_in[3];
    const float* cv       = (const float*)d_in[4];
    const int*   nitp     = (const int*)d_in[5];

    int G  = in_sizes[1];
    int BT = in_sizes[0];
    // out_size = 4*B*G*T + B  with  B*T = BT  ->  B = out_size - 4*G*BT
    int B = out_size - 4 * G * BT;
    if (B <= 0) B = 1;
    int T = BT / B;

    double L = spectral_norm_K(G);
    float tau = (float)(0.9 / L);

    float* out = (float*)d_out;
    int wpb = (T + 1) / 2;              // warps per block (one per 2 timesteps)
    if (wpb > 16) wpb = 16;             // safety: T <= 32 assumed for block fit
    pdhg_fused_kernel<<<B, wpb * 32>>>(
        forecast, pminv, pmaxv, bv, cv, nitp, out, G, B, T, tau);
}